// round 14
// baseline (speedup 1.0000x reference)
#include <cuda_runtime.h>
#include <cuda_fp16.h>
#include <math.h>

#define NN 100000
#define NE 1600000
#define SCAN_BS 512
#define NBLK ((NN + SCAN_BS - 1) / SCAN_BS)   // 196

// -------- device scratch (allocation-free rule: __device__ globals) --------
__device__ float  g_deginv[NN];
__device__ int    g_degi[NN];
__device__ int    g_cursor[NN];               // seeded with rowptr by scan_c
__device__ int    g_rowptr[NN + 1];
__device__ int    g_rowtmp[NN];
__device__ int    g_blocksum[NBLK];
__device__ int    g_blockoff[NBLK];
__device__ int    g_col[NE];                  // CSR: src ids grouped by dst
__device__ __half g_bufAh[NN * 64];           // yl (fp16)
__device__ __half g_bufBh[NN * 64];           // yr (fp16, layers 0/1)
__device__ float  g_bufB[NN * 64];            // yr (fp32, final layer)
__device__ __half g_h16[NN * 64];             // activations, fp16

// ---------------------------------------------------------------------------
// CSR build
// ---------------------------------------------------------------------------
__global__ void zero_int_kernel() {
    int i = blockIdx.x * blockDim.x + threadIdx.x;
    if (i < NN) g_degi[i] = 0;
}

__global__ void deg_count_kernel(const int* __restrict__ dst) {
    int e = blockIdx.x * blockDim.x + threadIdx.x;
    if (e < NE) atomicAdd(&g_degi[dst[e]], 1);
}

__global__ void scan_a_kernel() {
    __shared__ int s[SCAN_BS];
    int t = threadIdx.x;
    int i = blockIdx.x * SCAN_BS + t;
    int v = (i < NN) ? g_degi[i] : 0;
    s[t] = v;
    __syncthreads();
#pragma unroll
    for (int off = 1; off < SCAN_BS; off <<= 1) {
        int x = (t >= off) ? s[t - off] : 0;
        __syncthreads();
        s[t] += x;
        __syncthreads();
    }
    if (i < NN) g_rowtmp[i] = s[t] - v;           // exclusive
    if (t == SCAN_BS - 1) g_blocksum[blockIdx.x] = s[t];
}

__global__ void scan_b_kernel() {
    __shared__ int s[256];
    int t = threadIdx.x;
    int v = (t < NBLK) ? g_blocksum[t] : 0;
    s[t] = v;
    __syncthreads();
#pragma unroll
    for (int off = 1; off < 256; off <<= 1) {
        int x = (t >= off) ? s[t - off] : 0;
        __syncthreads();
        s[t] += x;
        __syncthreads();
    }
    if (t < NBLK) g_blockoff[t] = s[t] - v;       // exclusive
}

__global__ void scan_c_kernel() {
    int i = blockIdx.x * blockDim.x + threadIdx.x;
    if (i < NN) {
        int rp = g_rowtmp[i] + g_blockoff[i / SCAN_BS];
        g_rowptr[i] = rp;
        g_cursor[i] = rp;                          // absolute cursor seed
        g_deginv[i] = 1.0f / fmaxf((float)g_degi[i], 1.0f);
    }
    if (i == 0) g_rowptr[NN] = NE;
}

__global__ void csr_fill_kernel(const int* __restrict__ src,
                                const int* __restrict__ dst) {
    int e = blockIdx.x * blockDim.x + threadIdx.x;
    if (e >= NE) return;
    int pos = atomicAdd(&g_cursor[dst[e]], 1);     // absolute position
    g_col[pos] = src[e];
}

// ---------------------------------------------------------------------------
// fp16 pack helpers + f16 MMA
__device__ __forceinline__ unsigned pack_h2(float a, float b) {
    __half2 h = __floats2half2_rn(a, b);
    return *reinterpret_cast<unsigned*>(&h);
}
__device__ __forceinline__ unsigned pack_2h(__half a, __half b) {
    __half2 h = __halves2half2(a, b);
    return *reinterpret_cast<unsigned*>(&h);
}
__device__ __forceinline__ void mma_f16(float* d,
                                        unsigned a0, unsigned a1,
                                        unsigned a2, unsigned a3,
                                        unsigned b0, unsigned b1) {
    asm("mma.sync.aligned.m16n8k16.row.col.f32.f16.f16.f32 "
        "{%0,%1,%2,%3}, {%4,%5,%6,%7}, {%8,%9}, {%0,%1,%2,%3};"
        : "+f"(d[0]), "+f"(d[1]), "+f"(d[2]), "+f"(d[3])
        : "r"(a0), "r"(a1), "r"(a2), "r"(a3), "r"(b0), "r"(b1));
}

// ---------------------------------------------------------------------------
// Dual projection via fp16 tensor cores.
// FROM_X: read fp32 x directly, converting inline (layer 0).
// YR16:   store yr as fp16 (layers 0/1: h is fp16-rounded right after, so
//         fp16 yr adds only a same-order rounding term); else fp32.
template<int DOUT, bool FROM_X, bool YR16>
__global__ void __launch_bounds__(256)
gemm_dual_kernel(const float* __restrict__ x,
                 const float* __restrict__ Wl,
                 const float* __restrict__ Wr,
                 const float* __restrict__ bias) {
    constexpr int JT    = DOUT / 8;
    constexpr int FRAGS = 4 * JT;                // (kb, jt), kb of 16
    constexpr int FSZ   = FRAGS * 64;

    __shared__ unsigned sBl[FSZ];                // Wl fp16 pairs
    __shared__ unsigned sBrh[FSZ];               // Wr hi fp16 pairs
    __shared__ unsigned sBrl[FSZ];               // Wr lo fp16 pairs

    const int t    = threadIdx.x;
    const int wid  = t >> 5;
    const int lane = t & 31;
    const int gid  = lane >> 2;
    const int tig  = lane & 3;

    for (int idx = t; idx < FSZ; idx += 256) {
        const int frag = idx >> 6;
        const int li   = idx & 63;
        const int ln   = li >> 1;
        const int i    = li & 1;
        const int kb   = frag / JT;
        const int jt   = frag % JT;
        const int k    = kb * 16 + 2 * (ln & 3) + 8 * i;
        const int j    = jt * 8 + (ln >> 2);
        sBl[idx] = pack_h2(Wl[k * DOUT + j], Wl[(k + 1) * DOUT + j]);
        const float wr0 = Wr[k * DOUT + j];
        const float wr1 = Wr[(k + 1) * DOUT + j];
        const __half h0 = __float2half_rn(wr0);
        const __half h1 = __float2half_rn(wr1);
        sBrh[idx] = pack_2h(h0, h1);
        sBrl[idx] = pack_h2(wr0 - __half2float(h0), wr1 - __half2float(h1));
    }
    __syncthreads();

    const int node0 = blockIdx.x * 128 + wid * 16;
    const int r0 = node0 + gid;
    const bool ok0 = (r0 < NN);
    const bool ok1 = (r0 + 8 < NN);

    float dL[JT][4], dR[JT][4];
#pragma unroll
    for (int jt = 0; jt < JT; jt++) {
        float bc0 = bias[jt * 8 + 2 * tig];
        float bc1 = bias[jt * 8 + 2 * tig + 1];
        dL[jt][0] = dL[jt][1] = dL[jt][2] = dL[jt][3] = 0.f;
        dR[jt][0] = bc0; dR[jt][1] = bc1;
        dR[jt][2] = bc0; dR[jt][3] = bc1;
    }

#pragma unroll
    for (int kb = 0; kb < 4; kb++) {
        const int k0 = kb * 16;
        unsigned a0, a1, a2, a3;
        if (FROM_X) {
            a0 = ok0 ? pack_h2(x[(size_t)r0 * 64 + k0 + 2 * tig],
                               x[(size_t)r0 * 64 + k0 + 2 * tig + 1]) : 0u;
            a1 = ok1 ? pack_h2(x[(size_t)(r0 + 8) * 64 + k0 + 2 * tig],
                               x[(size_t)(r0 + 8) * 64 + k0 + 2 * tig + 1]) : 0u;
            a2 = ok0 ? pack_h2(x[(size_t)r0 * 64 + k0 + 2 * tig + 8],
                               x[(size_t)r0 * 64 + k0 + 2 * tig + 9]) : 0u;
            a3 = ok1 ? pack_h2(x[(size_t)(r0 + 8) * 64 + k0 + 2 * tig + 8],
                               x[(size_t)(r0 + 8) * 64 + k0 + 2 * tig + 9]) : 0u;
        } else {
            a0 = ok0 ? *(const unsigned*)&g_h16[(size_t)r0 * 64 + k0 + 2 * tig] : 0u;
            a1 = ok1 ? *(const unsigned*)&g_h16[(size_t)(r0 + 8) * 64 + k0 + 2 * tig] : 0u;
            a2 = ok0 ? *(const unsigned*)&g_h16[(size_t)r0 * 64 + k0 + 2 * tig + 8] : 0u;
            a3 = ok1 ? *(const unsigned*)&g_h16[(size_t)(r0 + 8) * 64 + k0 + 2 * tig + 8] : 0u;
        }

#pragma unroll
        for (int jt = 0; jt < JT; jt++) {
            const int fbase = (kb * JT + jt) * 64 + lane * 2;
            const uint2 bl = *(const uint2*)&sBl[fbase];
            const uint2 bh = *(const uint2*)&sBrh[fbase];
            const uint2 bo = *(const uint2*)&sBrl[fbase];
            mma_f16(dL[jt], a0, a1, a2, a3, bl.x, bl.y);
            mma_f16(dR[jt], a0, a1, a2, a3, bh.x, bh.y);
            mma_f16(dR[jt], a0, a1, a2, a3, bo.x, bo.y);
        }
    }

#pragma unroll
    for (int jt = 0; jt < JT; jt++) {
        const int j0 = jt * 8 + 2 * tig;
        if (ok0) {
            *(__half2*)&g_bufAh[(size_t)r0 * DOUT + j0] =
                __floats2half2_rn(dL[jt][0], dL[jt][1]);
            if (YR16)
                *(__half2*)&g_bufBh[(size_t)r0 * DOUT + j0] =
                    __floats2half2_rn(dR[jt][0], dR[jt][1]);
            else
                *(float2*)&g_bufB[(size_t)r0 * DOUT + j0] =
                    make_float2(dR[jt][0], dR[jt][1]);
        }
        if (ok1) {
            *(__half2*)&g_bufAh[(size_t)(r0 + 8) * DOUT + j0] =
                __floats2half2_rn(dL[jt][2], dL[jt][3]);
            if (YR16)
                *(__half2*)&g_bufBh[(size_t)(r0 + 8) * DOUT + j0] =
                    __floats2half2_rn(dR[jt][2], dR[jt][3]);
            else
                *(float2*)&g_bufB[(size_t)(r0 + 8) * DOUT + j0] =
                    make_float2(dR[jt][2], dR[jt][3]);
        }
    }
}

// ---------------------------------------------------------------------------
// Fused gather + epilogue: out[n] = [ELU]( mean_e yl[col[e]] + yr[n] )
// 2-way unrolled edge loop, dual fp32 accumulator sets for MLP.
template<int F, bool DO_ELU, bool TO_GH, bool YR16>
__global__ void __launch_bounds__(256)
gather_kernel(float* __restrict__ out_param) {
    constexpr int L = F / 8;               // lanes/node: 8 (F=64) or 4 (F=32)
    const int t    = threadIdx.x;
    const int grp  = t / L;
    const int lane = t % L;
    const int node = blockIdx.x * (256 / L) + grp;
    if (node >= NN) return;

    const int beg = g_rowptr[node];
    const int end = g_rowptr[node + 1];
    const __half* __restrict__ A = g_bufAh;

    float a[8] = {0.f, 0.f, 0.f, 0.f, 0.f, 0.f, 0.f, 0.f};
    float b[8] = {0.f, 0.f, 0.f, 0.f, 0.f, 0.f, 0.f, 0.f};
    int e = beg;
    for (; e + 2 <= end; e += 2) {
        const int s0 = g_col[e];
        const int s1 = g_col[e + 1];
        const uint4 v0 = *(const uint4*)&A[(size_t)s0 * F + lane * 8];
        const uint4 v1 = *(const uint4*)&A[(size_t)s1 * F + lane * 8];
        const __half2* h0 = (const __half2*)&v0;
        const __half2* h1 = (const __half2*)&v1;
#pragma unroll
        for (int i = 0; i < 4; i++) {
            float2 f0 = __half22float2(h0[i]);
            float2 f1 = __half22float2(h1[i]);
            a[2 * i] += f0.x; a[2 * i + 1] += f0.y;
            b[2 * i] += f1.x; b[2 * i + 1] += f1.y;
        }
    }
    if (e < end) {
        const int s0 = g_col[e];
        const uint4 v0 = *(const uint4*)&A[(size_t)s0 * F + lane * 8];
        const __half2* h0 = (const __half2*)&v0;
#pragma unroll
        for (int i = 0; i < 4; i++) {
            float2 f0 = __half22float2(h0[i]);
            a[2 * i] += f0.x; a[2 * i + 1] += f0.y;
        }
    }
#pragma unroll
    for (int i = 0; i < 8; i++) a[i] += b[i];

    const float di = g_deginv[node];
    float r[8];
    if (YR16) {
        const uint4 rv = *(const uint4*)&g_bufBh[(size_t)node * F + lane * 8];
        const __half2* rp = (const __half2*)&rv;
#pragma unroll
        for (int i = 0; i < 4; i++) {
            float2 f = __half22float2(rp[i]);
            r[2 * i] = f.x; r[2 * i + 1] = f.y;
        }
    } else {
        const float4 r0 = *(const float4*)&g_bufB[(size_t)node * F + lane * 8];
        const float4 r1 = *(const float4*)&g_bufB[(size_t)node * F + lane * 8 + 4];
        r[0] = r0.x; r[1] = r0.y; r[2] = r0.z; r[3] = r0.w;
        r[4] = r1.x; r[5] = r1.y; r[6] = r1.z; r[7] = r1.w;
    }

    float o[8];
#pragma unroll
    for (int i = 0; i < 8; i++) o[i] = fmaf(a[i], di, r[i]);
    if (DO_ELU) {
#pragma unroll
        for (int i = 0; i < 8; i++)
            o[i] = (o[i] > 0.f) ? o[i] : expm1f(o[i]);
    }
    if (TO_GH) {
        uint4 u;
        u.x = pack_h2(o[0], o[1]);
        u.y = pack_h2(o[2], o[3]);
        u.z = pack_h2(o[4], o[5]);
        u.w = pack_h2(o[6], o[7]);
        *(uint4*)&g_h16[(size_t)node * F + lane * 8] = u;
    } else {
        *(float4*)&out_param[(size_t)node * F + lane * 8] =
            make_float4(o[0], o[1], o[2], o[3]);
        *(float4*)&out_param[(size_t)node * F + lane * 8 + 4] =
            make_float4(o[4], o[5], o[6], o[7]);
    }
}

// ---------------------------------------------------------------------------
extern "C" void kernel_launch(void* const* d_in, const int* in_sizes, int n_in,
                              void* d_out, int out_size) {
    const float* x   = (const float*)d_in[0];
    const int*   ei  = (const int*)d_in[1];
    const float* Wl0 = (const float*)d_in[2];
    const float* Wr0 = (const float*)d_in[3];
    const float* b0  = (const float*)d_in[4];
    const float* Wl1 = (const float*)d_in[5];
    const float* Wr1 = (const float*)d_in[6];
    const float* b1  = (const float*)d_in[7];
    const float* Wl2 = (const float*)d_in[8];
    const float* Wr2 = (const float*)d_in[9];
    const float* b2  = (const float*)d_in[10];
    float* out = (float*)d_out;

    const int* src = ei;
    const int* dst = ei + NE;

    const int TPB = 256;
    const int gemm_blocks = (NN + 127) / 128;
    const int gather_blocks64 = (NN + 31) / 32;
    const int gather_blocks32 = (NN + 63) / 64;

    static cudaStream_t s_side = nullptr;
    static cudaEvent_t  s_fork = nullptr, s_join = nullptr;
    if (s_side == nullptr) {
        cudaStreamCreateWithFlags(&s_side, cudaStreamNonBlocking);
        cudaEventCreateWithFlags(&s_fork, cudaEventDisableTiming);
        cudaEventCreateWithFlags(&s_join, cudaEventDisableTiming);
    }

    // ---- fork: CSR build on side stream, GEMM0 on main stream ----
    cudaEventRecord(s_fork, 0);
    cudaStreamWaitEvent(s_side, s_fork, 0);

    zero_int_kernel<<<(NN + TPB - 1) / TPB, TPB, 0, s_side>>>();
    deg_count_kernel<<<(NE + TPB - 1) / TPB, TPB, 0, s_side>>>(dst);
    scan_a_kernel<<<NBLK, SCAN_BS, 0, s_side>>>();
    scan_b_kernel<<<1, 256, 0, s_side>>>();
    scan_c_kernel<<<(NN + TPB - 1) / TPB, TPB, 0, s_side>>>();
    csr_fill_kernel<<<(NE + TPB - 1) / TPB, TPB, 0, s_side>>>(src, dst);
    cudaEventRecord(s_join, s_side);

    gemm_dual_kernel<64, true, true><<<gemm_blocks, 256>>>(x, Wl0, Wr0, b0);

    // ---- join: gather0 needs both CSR and bufAh/bufBh ----
    cudaStreamWaitEvent(0, s_join, 0);
    gather_kernel<64, true, true, true><<<gather_blocks64, 256>>>(nullptr);

    // ---- layer 1: 64 -> 64, ELU ----
    gemm_dual_kernel<64, false, true><<<gemm_blocks, 256>>>(nullptr, Wl1, Wr1, b1);
    gather_kernel<64, true, true, true><<<gather_blocks64, 256>>>(nullptr);

    // ---- layer 2: 64 -> 32, no activation, straight to d_out ----
    gemm_dual_kernel<32, false, false><<<gemm_blocks, 256>>>(nullptr, Wl2, Wr2, b2);
    gather_kernel<32, false, false, false><<<gather_blocks32, 256>>>(out);
}

// round 15
// speedup vs baseline: 1.0243x; 1.0243x over previous
#include <cuda_runtime.h>
#include <cuda_fp16.h>
#include <math.h>

#define NN 100000
#define NE 1600000
#define SCAN_BS 512
#define NBLK ((NN + SCAN_BS - 1) / SCAN_BS)   // 196

// -------- device scratch (allocation-free rule: __device__ globals) --------
__device__ float  g_deginv[NN];
__device__ int    g_degi[NN];
__device__ int    g_cursor[NN];               // seeded with rowptr by the scan
__device__ int    g_rowptr[NN + 1];
__device__ unsigned long long g_scanstate[NBLK];  // lookback: (flag<<32)|value
__device__ int    g_col[NE];                  // CSR: src ids grouped by dst
__device__ __half g_bufAh[NN * 64];           // yl (fp16: gather reads this)
__device__ float  g_bufB[NN * 64];            // yr (fp32)
__device__ __half g_h16[NN * 64];             // activations, fp16 (GEMM A-feed)

// ---------------------------------------------------------------------------
// CSR build: zero -> deg_count -> lookback scan -> fill   (4 kernels)
// ---------------------------------------------------------------------------
__global__ void zero_int_kernel() {
    int i = blockIdx.x * blockDim.x + threadIdx.x;
    if (i < NN) g_degi[i] = 0;
    if (i < NBLK) g_scanstate[i] = 0ULL;
}

__global__ void deg_count_kernel(const int* __restrict__ dst) {
    int e = blockIdx.x * blockDim.x + threadIdx.x;
    if (e < NE) atomicAdd(&g_degi[dst[e]], 1);
}

// Single-pass decoupled-lookback exclusive scan of g_degi -> rowptr/cursor,
// plus deginv. flag: 0=invalid, 1=aggregate ready, 2=inclusive prefix ready.
__global__ void scan_lookback_kernel() {
    __shared__ int s[SCAN_BS];
    __shared__ int s_prefix;
    const int t = threadIdx.x;
    const int b = blockIdx.x;
    const int i = b * SCAN_BS + t;
    const int v = (i < NN) ? g_degi[i] : 0;
    s[t] = v;
    __syncthreads();
#pragma unroll
    for (int off = 1; off < SCAN_BS; off <<= 1) {
        int x = (t >= off) ? s[t - off] : 0;
        __syncthreads();
        s[t] += x;
        __syncthreads();
    }
    const int agg = s[SCAN_BS - 1];

    if (t == 0) {
        if (b == 0) {
            __threadfence();
            atomicExch(&g_scanstate[0], (2ULL << 32) | (unsigned)agg);
            s_prefix = 0;
        } else {
            __threadfence();
            atomicExch(&g_scanstate[b], (1ULL << 32) | (unsigned)agg);
            int running = 0;
            int p = b - 1;
            while (true) {
                unsigned long long st;
                do { st = atomicAdd(&g_scanstate[p], 0ULL); } while ((st >> 32) == 0ULL);
                running += (int)(st & 0xffffffffULL);
                if ((st >> 32) == 2ULL) break;
                p--;
            }
            __threadfence();
            atomicExch(&g_scanstate[b], (2ULL << 32) | (unsigned)(running + agg));
            s_prefix = running;
        }
    }
    __syncthreads();

    if (i < NN) {
        const int rp = s_prefix + s[t] - v;        // exclusive prefix
        g_rowptr[i] = rp;
        g_cursor[i] = rp;                          // absolute cursor seed
        g_deginv[i] = 1.0f / fmaxf((float)g_degi[i], 1.0f);
    }
    if (i == 0) g_rowptr[NN] = NE;
}

__global__ void csr_fill_kernel(const int* __restrict__ src,
                                const int* __restrict__ dst) {
    int e = blockIdx.x * blockDim.x + threadIdx.x;
    if (e >= NE) return;
    int pos = atomicAdd(&g_cursor[dst[e]], 1);     // absolute position
    g_col[pos] = src[e];
}

// ---------------------------------------------------------------------------
// fp16 pack helpers + f16 MMA
__device__ __forceinline__ unsigned pack_h2(float a, float b) {
    __half2 h = __floats2half2_rn(a, b);
    return *reinterpret_cast<unsigned*>(&h);
}
__device__ __forceinline__ unsigned pack_2h(__half a, __half b) {
    __half2 h = __halves2half2(a, b);
    return *reinterpret_cast<unsigned*>(&h);
}
__device__ __forceinline__ void mma_f16(float* d,
                                        unsigned a0, unsigned a1,
                                        unsigned a2, unsigned a3,
                                        unsigned b0, unsigned b1) {
    asm("mma.sync.aligned.m16n8k16.row.col.f32.f16.f16.f32 "
        "{%0,%1,%2,%3}, {%4,%5,%6,%7}, {%8,%9}, {%0,%1,%2,%3};"
        : "+f"(d[0]), "+f"(d[1]), "+f"(d[2]), "+f"(d[3])
        : "r"(a0), "r"(a1), "r"(a2), "r"(a3), "r"(b0), "r"(b1));
}

// ---------------------------------------------------------------------------
// Convert fp32 input x -> fp16 activations (layer-0 A-feed).
__global__ void cvt_x_kernel(const float* __restrict__ x) {
    int i = blockIdx.x * blockDim.x + threadIdx.x;   // one per 8 elements
    if (i >= NN * 8) return;
    const float4 v0 = *(const float4*)&x[(size_t)i * 8];
    const float4 v1 = *(const float4*)&x[(size_t)i * 8 + 4];
    uint4 u;
    u.x = pack_h2(v0.x, v0.y);
    u.y = pack_h2(v0.z, v0.w);
    u.z = pack_h2(v1.x, v1.y);
    u.w = pack_h2(v1.z, v1.w);
    *(uint4*)&g_h16[(size_t)i * 8] = u;
}

// ---------------------------------------------------------------------------
// Dual projection via fp16 tensor cores, A = g_h16 (fp16 activations).
// yl: 1 fp16 MMA (precision matches fp16 storage).
// yr: 2 fp16 MMAs with exact hi/lo fp16 split of Wr.
template<int DOUT>
__global__ void __launch_bounds__(256)
gemm_dual_kernel(const float* __restrict__ Wl,
                 const float* __restrict__ Wr,
                 const float* __restrict__ bias) {
    constexpr int JT    = DOUT / 8;              // j-tiles (8 or 4)
    constexpr int FRAGS = 4 * JT;                // (kb, jt) fragments, kb of 16
    constexpr int FSZ   = FRAGS * 64;

    __shared__ unsigned sBl[FSZ];                // Wl fp16 pairs
    __shared__ unsigned sBrh[FSZ];               // Wr hi fp16 pairs
    __shared__ unsigned sBrl[FSZ];               // Wr lo fp16 pairs

    const int t    = threadIdx.x;
    const int wid  = t >> 5;
    const int lane = t & 31;
    const int gid  = lane >> 2;
    const int tig  = lane & 3;

    for (int idx = t; idx < FSZ; idx += 256) {
        const int frag = idx >> 6;
        const int li   = idx & 63;
        const int ln   = li >> 1;
        const int i    = li & 1;
        const int kb   = frag / JT;
        const int jt   = frag % JT;
        const int k    = kb * 16 + 2 * (ln & 3) + 8 * i;
        const int j    = jt * 8 + (ln >> 2);
        sBl[idx] = pack_h2(Wl[k * DOUT + j], Wl[(k + 1) * DOUT + j]);
        const float wr0 = Wr[k * DOUT + j];
        const float wr1 = Wr[(k + 1) * DOUT + j];
        const __half h0 = __float2half_rn(wr0);
        const __half h1 = __float2half_rn(wr1);
        sBrh[idx] = pack_2h(h0, h1);
        sBrl[idx] = pack_h2(wr0 - __half2float(h0), wr1 - __half2float(h1));
    }
    __syncthreads();

    const int node0 = blockIdx.x * 128 + wid * 16;
    const int r0 = node0 + gid;
    const bool ok0 = (r0 < NN);
    const bool ok1 = (r0 + 8 < NN);

    float dL[JT][4], dR[JT][4];
#pragma unroll
    for (int jt = 0; jt < JT; jt++) {
        float bc0 = bias[jt * 8 + 2 * tig];
        float bc1 = bias[jt * 8 + 2 * tig + 1];
        dL[jt][0] = dL[jt][1] = dL[jt][2] = dL[jt][3] = 0.f;
        dR[jt][0] = bc0; dR[jt][1] = bc1;
        dR[jt][2] = bc0; dR[jt][3] = bc1;
    }

#pragma unroll
    for (int kb = 0; kb < 4; kb++) {
        const int k0 = kb * 16;
        const unsigned a0 = ok0 ? *(const unsigned*)&g_h16[(size_t)r0 * 64 + k0 + 2 * tig] : 0u;
        const unsigned a1 = ok1 ? *(const unsigned*)&g_h16[(size_t)(r0 + 8) * 64 + k0 + 2 * tig] : 0u;
        const unsigned a2 = ok0 ? *(const unsigned*)&g_h16[(size_t)r0 * 64 + k0 + 2 * tig + 8] : 0u;
        const unsigned a3 = ok1 ? *(const unsigned*)&g_h16[(size_t)(r0 + 8) * 64 + k0 + 2 * tig + 8] : 0u;

#pragma unroll
        for (int jt = 0; jt < JT; jt++) {
            const int fbase = (kb * JT + jt) * 64 + lane * 2;
            const uint2 bl = *(const uint2*)&sBl[fbase];
            const uint2 bh = *(const uint2*)&sBrh[fbase];
            const uint2 bo = *(const uint2*)&sBrl[fbase];
            mma_f16(dL[jt], a0, a1, a2, a3, bl.x, bl.y);
            mma_f16(dR[jt], a0, a1, a2, a3, bh.x, bh.y);
            mma_f16(dR[jt], a0, a1, a2, a3, bo.x, bo.y);
        }
    }

    // epilogue: yl -> fp16, yr -> fp32
#pragma unroll
    for (int jt = 0; jt < JT; jt++) {
        const int j0 = jt * 8 + 2 * tig;
        if (ok0) {
            *(__half2*)&g_bufAh[(size_t)r0 * DOUT + j0] =
                __floats2half2_rn(dL[jt][0], dL[jt][1]);
            *(float2*)&g_bufB[(size_t)r0 * DOUT + j0] = make_float2(dR[jt][0], dR[jt][1]);
        }
        if (ok1) {
            *(__half2*)&g_bufAh[(size_t)(r0 + 8) * DOUT + j0] =
                __floats2half2_rn(dL[jt][2], dL[jt][3]);
            *(float2*)&g_bufB[(size_t)(r0 + 8) * DOUT + j0] = make_float2(dR[jt][2], dR[jt][3]);
        }
    }
}

// ---------------------------------------------------------------------------
// Fused gather + epilogue: out[n] = [ELU]( mean_e yl_h16[col[e]] + yr[n] )
// yl fp16: one uint4 (8 halves) per lane per edge; fp32 accumulation.
template<int F, bool DO_ELU, bool TO_GH>
__global__ void __launch_bounds__(256)
gather_kernel(float* __restrict__ out_param) {
    constexpr int L = F / 8;               // lanes/node: 8 (F=64) or 4 (F=32)
    const int t    = threadIdx.x;
    const int grp  = t / L;
    const int lane = t % L;
    const int node = blockIdx.x * (256 / L) + grp;
    if (node >= NN) return;

    const int beg = g_rowptr[node];
    const int end = g_rowptr[node + 1];
    const __half* __restrict__ A = g_bufAh;

    float a[8] = {0.f, 0.f, 0.f, 0.f, 0.f, 0.f, 0.f, 0.f};
    for (int e = beg; e < end; e++) {
        const int s = g_col[e];
        const uint4 v = *(const uint4*)&A[(size_t)s * F + lane * 8];
        const __half2* hp = (const __half2*)&v;
        float2 f0 = __half22float2(hp[0]);
        float2 f1 = __half22float2(hp[1]);
        float2 f2 = __half22float2(hp[2]);
        float2 f3 = __half22float2(hp[3]);
        a[0] += f0.x; a[1] += f0.y;
        a[2] += f1.x; a[3] += f1.y;
        a[4] += f2.x; a[5] += f2.y;
        a[6] += f3.x; a[7] += f3.y;
    }

    const float di = g_deginv[node];
    const float4 r0 = *(const float4*)&g_bufB[(size_t)node * F + lane * 8];
    const float4 r1 = *(const float4*)&g_bufB[(size_t)node * F + lane * 8 + 4];
    float o[8];
    o[0] = fmaf(a[0], di, r0.x);
    o[1] = fmaf(a[1], di, r0.y);
    o[2] = fmaf(a[2], di, r0.z);
    o[3] = fmaf(a[3], di, r0.w);
    o[4] = fmaf(a[4], di, r1.x);
    o[5] = fmaf(a[5], di, r1.y);
    o[6] = fmaf(a[6], di, r1.z);
    o[7] = fmaf(a[7], di, r1.w);
    if (DO_ELU) {
#pragma unroll
        for (int i = 0; i < 8; i++)
            o[i] = (o[i] > 0.f) ? o[i] : expm1f(o[i]);
    }
    if (TO_GH) {
        uint4 u;
        u.x = pack_h2(o[0], o[1]);
        u.y = pack_h2(o[2], o[3]);
        u.z = pack_h2(o[4], o[5]);
        u.w = pack_h2(o[6], o[7]);
        *(uint4*)&g_h16[(size_t)node * F + lane * 8] = u;
    } else {
        *(float4*)&out_param[(size_t)node * F + lane * 8] =
            make_float4(o[0], o[1], o[2], o[3]);
        *(float4*)&out_param[(size_t)node * F + lane * 8 + 4] =
            make_float4(o[4], o[5], o[6], o[7]);
    }
}

// ---------------------------------------------------------------------------
extern "C" void kernel_launch(void* const* d_in, const int* in_sizes, int n_in,
                              void* d_out, int out_size) {
    const float* x   = (const float*)d_in[0];
    const int*   ei  = (const int*)d_in[1];
    const float* Wl0 = (const float*)d_in[2];
    const float* Wr0 = (const float*)d_in[3];
    const float* b0  = (const float*)d_in[4];
    const float* Wl1 = (const float*)d_in[5];
    const float* Wr1 = (const float*)d_in[6];
    const float* b1  = (const float*)d_in[7];
    const float* Wl2 = (const float*)d_in[8];
    const float* Wr2 = (const float*)d_in[9];
    const float* b2  = (const float*)d_in[10];
    float* out = (float*)d_out;

    const int* src = ei;
    const int* dst = ei + NE;

    const int TPB = 256;
    const int gemm_blocks = (NN + 127) / 128;     // 782
    const int gather_blocks64 = (NN + 31) / 32;   // 32 nodes/block (L=8)
    const int gather_blocks32 = (NN + 63) / 64;   // 64 nodes/block (L=4)

    // One-time host-side setup (stream + events only).
    static cudaStream_t s_side = nullptr;
    static cudaEvent_t  s_fork = nullptr, s_join = nullptr;
    if (s_side == nullptr) {
        cudaStreamCreateWithFlags(&s_side, cudaStreamNonBlocking);
        cudaEventCreateWithFlags(&s_fork, cudaEventDisableTiming);
        cudaEventCreateWithFlags(&s_join, cudaEventDisableTiming);
    }

    // ---- fork: CSR build on side stream, cvt+GEMM0 on main stream ----
    cudaEventRecord(s_fork, 0);
    cudaStreamWaitEvent(s_side, s_fork, 0);

    zero_int_kernel<<<(NN + TPB - 1) / TPB, TPB, 0, s_side>>>();
    deg_count_kernel<<<(NE + TPB - 1) / TPB, TPB, 0, s_side>>>(dst);
    scan_lookback_kernel<<<NBLK, SCAN_BS, 0, s_side>>>();
    csr_fill_kernel<<<(NE + TPB - 1) / TPB, TPB, 0, s_side>>>(src, dst);
    cudaEventRecord(s_join, s_side);

    cvt_x_kernel<<<(NN * 8 + TPB - 1) / TPB, TPB>>>(x);
    gemm_dual_kernel<64><<<gemm_blocks, 256>>>(Wl0, Wr0, b0);

    // ---- join: gather0 needs both CSR and bufAh/bufB ----
    cudaStreamWaitEvent(0, s_join, 0);
    gather_kernel<64, true, true><<<gather_blocks64, 256>>>(nullptr);

    // ---- layer 1: 64 -> 64, ELU ----
    gemm_dual_kernel<64><<<gemm_blocks, 256>>>(Wl1, Wr1, b1);
    gather_kernel<64, true, true><<<gather_blocks64, 256>>>(nullptr);

    // ---- layer 2: 64 -> 32, no activation, straight to d_out ----
    gemm_dual_kernel<32><<<gemm_blocks, 256>>>(Wl2, Wr2, b2);
    gather_kernel<32, false, false><<<gather_blocks32, 256>>>(out);
}

// round 16
// speedup vs baseline: 1.0289x; 1.0045x over previous
#include <cuda_runtime.h>
#include <cuda_fp16.h>
#include <math.h>

#define NN 100000
#define NE 1600000
#define SCAN_BS 512
#define NBLK ((NN + SCAN_BS - 1) / SCAN_BS)   // 196

// -------- device scratch (allocation-free rule: __device__ globals) --------
__device__ float  g_deginv[NN];
__device__ int    g_degi[NN];
__device__ int    g_rank[NE];                 // edge's rank within its dst row
__device__ int    g_rowptr[NN + 1];
__device__ unsigned long long g_scanstate[NBLK];  // lookback: (flag<<32)|value
__device__ int    g_col[NE];                  // CSR: src ids grouped by dst
__device__ __half g_bufAh[NN * 64];           // yl (fp16: gather reads this)
__device__ __half g_bufBh[NN * 64];           // yr (fp16, layers 0/1)
__device__ float  g_bufB[NN * 64];            // yr (fp32, final layer)
__device__ __half g_h16[NN * 64];             // activations, fp16 (GEMM A-feed)

// ---------------------------------------------------------------------------
// CSR build: zero -> deg_count(+rank) -> lookback scan -> fill (atomic-free)
// ---------------------------------------------------------------------------
__global__ void zero_int_kernel() {
    int i = blockIdx.x * blockDim.x + threadIdx.x;
    if (i < NN) g_degi[i] = 0;
    if (i < NBLK) g_scanstate[i] = 0ULL;
}

__global__ void deg_count_kernel(const int* __restrict__ dst) {
    int e = blockIdx.x * blockDim.x + threadIdx.x;
    if (e < NE) g_rank[e] = atomicAdd(&g_degi[dst[e]], 1);
}

// Single-pass decoupled-lookback exclusive scan of g_degi -> rowptr + deginv.
__global__ void scan_lookback_kernel() {
    __shared__ int s[SCAN_BS];
    __shared__ int s_prefix;
    const int t = threadIdx.x;
    const int b = blockIdx.x;
    const int i = b * SCAN_BS + t;
    const int v = (i < NN) ? g_degi[i] : 0;
    s[t] = v;
    __syncthreads();
#pragma unroll
    for (int off = 1; off < SCAN_BS; off <<= 1) {
        int x = (t >= off) ? s[t - off] : 0;
        __syncthreads();
        s[t] += x;
        __syncthreads();
    }
    const int agg = s[SCAN_BS - 1];

    if (t == 0) {
        if (b == 0) {
            __threadfence();
            atomicExch(&g_scanstate[0], (2ULL << 32) | (unsigned)agg);
            s_prefix = 0;
        } else {
            __threadfence();
            atomicExch(&g_scanstate[b], (1ULL << 32) | (unsigned)agg);
            int running = 0;
            int p = b - 1;
            while (true) {
                unsigned long long st;
                do { st = atomicAdd(&g_scanstate[p], 0ULL); } while ((st >> 32) == 0ULL);
                running += (int)(st & 0xffffffffULL);
                if ((st >> 32) == 2ULL) break;
                p--;
            }
            __threadfence();
            atomicExch(&g_scanstate[b], (2ULL << 32) | (unsigned)(running + agg));
            s_prefix = running;
        }
    }
    __syncthreads();

    if (i < NN) {
        g_rowptr[i] = s_prefix + s[t] - v;         // exclusive prefix
        g_deginv[i] = 1.0f / fmaxf((float)g_degi[i], 1.0f);
    }
    if (i == 0) g_rowptr[NN] = NE;
}

// Atomic-free fill: position = rowptr[dst] + precomputed rank.
// No dependent-atomic chain -> full memory-level parallelism.
__global__ void csr_fill_kernel(const int* __restrict__ src,
                                const int* __restrict__ dst) {
    int e = blockIdx.x * blockDim.x + threadIdx.x;
    if (e >= NE) return;
    g_col[g_rowptr[dst[e]] + g_rank[e]] = src[e];
}

// ---------------------------------------------------------------------------
// fp16 pack helpers + f16 MMA
__device__ __forceinline__ unsigned pack_h2(float a, float b) {
    __half2 h = __floats2half2_rn(a, b);
    return *reinterpret_cast<unsigned*>(&h);
}
__device__ __forceinline__ unsigned pack_2h(__half a, __half b) {
    __half2 h = __halves2half2(a, b);
    return *reinterpret_cast<unsigned*>(&h);
}
__device__ __forceinline__ void mma_f16(float* d,
                                        unsigned a0, unsigned a1,
                                        unsigned a2, unsigned a3,
                                        unsigned b0, unsigned b1) {
    asm("mma.sync.aligned.m16n8k16.row.col.f32.f16.f16.f32 "
        "{%0,%1,%2,%3}, {%4,%5,%6,%7}, {%8,%9}, {%0,%1,%2,%3};"
        : "+f"(d[0]), "+f"(d[1]), "+f"(d[2]), "+f"(d[3])
        : "r"(a0), "r"(a1), "r"(a2), "r"(a3), "r"(b0), "r"(b1));
}

// ---------------------------------------------------------------------------
// Convert fp32 input x -> fp16 activations (layer-0 A-feed).
__global__ void cvt_x_kernel(const float* __restrict__ x) {
    int i = blockIdx.x * blockDim.x + threadIdx.x;   // one per 8 elements
    if (i >= NN * 8) return;
    const float4 v0 = *(const float4*)&x[(size_t)i * 8];
    const float4 v1 = *(const float4*)&x[(size_t)i * 8 + 4];
    uint4 u;
    u.x = pack_h2(v0.x, v0.y);
    u.y = pack_h2(v0.z, v0.w);
    u.z = pack_h2(v1.x, v1.y);
    u.w = pack_h2(v1.z, v1.w);
    *(uint4*)&g_h16[(size_t)i * 8] = u;
}

// ---------------------------------------------------------------------------
// Dual projection via fp16 tensor cores, A = g_h16 (fp16 activations).
// yl: 1 fp16 MMA.  yr: 2 fp16 MMAs (exact hi/lo fp16 split of Wr).
// YR16: store yr fp16 (layers 0/1; h is fp16-rounded right after anyway).
template<int DOUT, bool YR16>
__global__ void __launch_bounds__(256)
gemm_dual_kernel(const float* __restrict__ Wl,
                 const float* __restrict__ Wr,
                 const float* __restrict__ bias) {
    constexpr int JT    = DOUT / 8;              // j-tiles (8 or 4)
    constexpr int FRAGS = 4 * JT;                // (kb, jt) fragments, kb of 16
    constexpr int FSZ   = FRAGS * 64;

    __shared__ unsigned sBl[FSZ];                // Wl fp16 pairs
    __shared__ unsigned sBrh[FSZ];               // Wr hi fp16 pairs
    __shared__ unsigned sBrl[FSZ];               // Wr lo fp16 pairs

    const int t    = threadIdx.x;
    const int wid  = t >> 5;
    const int lane = t & 31;
    const int gid  = lane >> 2;
    const int tig  = lane & 3;

    for (int idx = t; idx < FSZ; idx += 256) {
        const int frag = idx >> 6;
        const int li   = idx & 63;
        const int ln   = li >> 1;
        const int i    = li & 1;
        const int kb   = frag / JT;
        const int jt   = frag % JT;
        const int k    = kb * 16 + 2 * (ln & 3) + 8 * i;
        const int j    = jt * 8 + (ln >> 2);
        sBl[idx] = pack_h2(Wl[k * DOUT + j], Wl[(k + 1) * DOUT + j]);
        const float wr0 = Wr[k * DOUT + j];
        const float wr1 = Wr[(k + 1) * DOUT + j];
        const __half h0 = __float2half_rn(wr0);
        const __half h1 = __float2half_rn(wr1);
        sBrh[idx] = pack_2h(h0, h1);
        sBrl[idx] = pack_h2(wr0 - __half2float(h0), wr1 - __half2float(h1));
    }
    __syncthreads();

    const int node0 = blockIdx.x * 128 + wid * 16;
    const int r0 = node0 + gid;
    const bool ok0 = (r0 < NN);
    const bool ok1 = (r0 + 8 < NN);

    float dL[JT][4], dR[JT][4];
#pragma unroll
    for (int jt = 0; jt < JT; jt++) {
        float bc0 = bias[jt * 8 + 2 * tig];
        float bc1 = bias[jt * 8 + 2 * tig + 1];
        dL[jt][0] = dL[jt][1] = dL[jt][2] = dL[jt][3] = 0.f;
        dR[jt][0] = bc0; dR[jt][1] = bc1;
        dR[jt][2] = bc0; dR[jt][3] = bc1;
    }

#pragma unroll
    for (int kb = 0; kb < 4; kb++) {
        const int k0 = kb * 16;
        const unsigned a0 = ok0 ? *(const unsigned*)&g_h16[(size_t)r0 * 64 + k0 + 2 * tig] : 0u;
        const unsigned a1 = ok1 ? *(const unsigned*)&g_h16[(size_t)(r0 + 8) * 64 + k0 + 2 * tig] : 0u;
        const unsigned a2 = ok0 ? *(const unsigned*)&g_h16[(size_t)r0 * 64 + k0 + 2 * tig + 8] : 0u;
        const unsigned a3 = ok1 ? *(const unsigned*)&g_h16[(size_t)(r0 + 8) * 64 + k0 + 2 * tig + 8] : 0u;

#pragma unroll
        for (int jt = 0; jt < JT; jt++) {
            const int fbase = (kb * JT + jt) * 64 + lane * 2;
            const uint2 bl = *(const uint2*)&sBl[fbase];
            const uint2 bh = *(const uint2*)&sBrh[fbase];
            const uint2 bo = *(const uint2*)&sBrl[fbase];
            mma_f16(dL[jt], a0, a1, a2, a3, bl.x, bl.y);
            mma_f16(dR[jt], a0, a1, a2, a3, bh.x, bh.y);
            mma_f16(dR[jt], a0, a1, a2, a3, bo.x, bo.y);
        }
    }

    // epilogue: yl -> fp16; yr -> fp16 (YR16) or fp32
#pragma unroll
    for (int jt = 0; jt < JT; jt++) {
        const int j0 = jt * 8 + 2 * tig;
        if (ok0) {
            *(__half2*)&g_bufAh[(size_t)r0 * DOUT + j0] =
                __floats2half2_rn(dL[jt][0], dL[jt][1]);
            if (YR16)
                *(__half2*)&g_bufBh[(size_t)r0 * DOUT + j0] =
                    __floats2half2_rn(dR[jt][0], dR[jt][1]);
            else
                *(float2*)&g_bufB[(size_t)r0 * DOUT + j0] =
                    make_float2(dR[jt][0], dR[jt][1]);
        }
        if (ok1) {
            *(__half2*)&g_bufAh[(size_t)(r0 + 8) * DOUT + j0] =
                __floats2half2_rn(dL[jt][2], dL[jt][3]);
            if (YR16)
                *(__half2*)&g_bufBh[(size_t)(r0 + 8) * DOUT + j0] =
                    __floats2half2_rn(dR[jt][2], dR[jt][3]);
            else
                *(float2*)&g_bufB[(size_t)(r0 + 8) * DOUT + j0] =
                    make_float2(dR[jt][2], dR[jt][3]);
        }
    }
}

// ---------------------------------------------------------------------------
// Fused gather + epilogue: out[n] = [ELU]( mean_e yl_h16[col[e]] + yr[n] )
// Simple loop (round-13 form); yr read fp16 (YR16) or fp32.
template<int F, bool DO_ELU, bool TO_GH, bool YR16>
__global__ void __launch_bounds__(256)
gather_kernel(float* __restrict__ out_param) {
    constexpr int L = F / 8;               // lanes/node: 8 (F=64) or 4 (F=32)
    const int t    = threadIdx.x;
    const int grp  = t / L;
    const int lane = t % L;
    const int node = blockIdx.x * (256 / L) + grp;
    if (node >= NN) return;

    const int beg = g_rowptr[node];
    const int end = g_rowptr[node + 1];
    const __half* __restrict__ A = g_bufAh;

    float a[8] = {0.f, 0.f, 0.f, 0.f, 0.f, 0.f, 0.f, 0.f};
    for (int e = beg; e < end; e++) {
        const int s = g_col[e];
        const uint4 v = *(const uint4*)&A[(size_t)s * F + lane * 8];
        const __half2* hp = (const __half2*)&v;
        float2 f0 = __half22float2(hp[0]);
        float2 f1 = __half22float2(hp[1]);
        float2 f2 = __half22float2(hp[2]);
        float2 f3 = __half22float2(hp[3]);
        a[0] += f0.x; a[1] += f0.y;
        a[2] += f1.x; a[3] += f1.y;
        a[4] += f2.x; a[5] += f2.y;
        a[6] += f3.x; a[7] += f3.y;
    }

    const float di = g_deginv[node];
    float r[8];
    if (YR16) {
        const uint4 rv = *(const uint4*)&g_bufBh[(size_t)node * F + lane * 8];
        const __half2* rp = (const __half2*)&rv;
#pragma unroll
        for (int i = 0; i < 4; i++) {
            float2 f = __half22float2(rp[i]);
            r[2 * i] = f.x; r[2 * i + 1] = f.y;
        }
    } else {
        const float4 r0 = *(const float4*)&g_bufB[(size_t)node * F + lane * 8];
        const float4 r1 = *(const float4*)&g_bufB[(size_t)node * F + lane * 8 + 4];
        r[0] = r0.x; r[1] = r0.y; r[2] = r0.z; r[3] = r0.w;
        r[4] = r1.x; r[5] = r1.y; r[6] = r1.z; r[7] = r1.w;
    }

    float o[8];
#pragma unroll
    for (int i = 0; i < 8; i++) o[i] = fmaf(a[i], di, r[i]);
    if (DO_ELU) {
#pragma unroll
        for (int i = 0; i < 8; i++)
            o[i] = (o[i] > 0.f) ? o[i] : expm1f(o[i]);
    }
    if (TO_GH) {
        uint4 u;
        u.x = pack_h2(o[0], o[1]);
        u.y = pack_h2(o[2], o[3]);
        u.z = pack_h2(o[4], o[5]);
        u.w = pack_h2(o[6], o[7]);
        *(uint4*)&g_h16[(size_t)node * F + lane * 8] = u;
    } else {
        *(float4*)&out_param[(size_t)node * F + lane * 8] =
            make_float4(o[0], o[1], o[2], o[3]);
        *(float4*)&out_param[(size_t)node * F + lane * 8 + 4] =
            make_float4(o[4], o[5], o[6], o[7]);
    }
}

// ---------------------------------------------------------------------------
extern "C" void kernel_launch(void* const* d_in, const int* in_sizes, int n_in,
                              void* d_out, int out_size) {
    const float* x   = (const float*)d_in[0];
    const int*   ei  = (const int*)d_in[1];
    const float* Wl0 = (const float*)d_in[2];
    const float* Wr0 = (const float*)d_in[3];
    const float* b0  = (const float*)d_in[4];
    const float* Wl1 = (const float*)d_in[5];
    const float* Wr1 = (const float*)d_in[6];
    const float* b1  = (const float*)d_in[7];
    const float* Wl2 = (const float*)d_in[8];
    const float* Wr2 = (const float*)d_in[9];
    const float* b2  = (const float*)d_in[10];
    float* out = (float*)d_out;

    const int* src = ei;
    const int* dst = ei + NE;

    const int TPB = 256;
    const int gemm_blocks = (NN + 127) / 128;     // 782
    const int gather_blocks64 = (NN + 31) / 32;   // 32 nodes/block (L=8)
    const int gather_blocks32 = (NN + 63) / 64;   // 64 nodes/block (L=4)

    // One-time host-side setup (stream + events only).
    static cudaStream_t s_side = nullptr;
    static cudaEvent_t  s_fork = nullptr, s_join = nullptr;
    if (s_side == nullptr) {
        cudaStreamCreateWithFlags(&s_side, cudaStreamNonBlocking);
        cudaEventCreateWithFlags(&s_fork, cudaEventDisableTiming);
        cudaEventCreateWithFlags(&s_join, cudaEventDisableTiming);
    }

    // ---- fork: CSR build on side stream, cvt+GEMM0 on main stream ----
    cudaEventRecord(s_fork, 0);
    cudaStreamWaitEvent(s_side, s_fork, 0);

    zero_int_kernel<<<(NN + TPB - 1) / TPB, TPB, 0, s_side>>>();
    deg_count_kernel<<<(NE + TPB - 1) / TPB, TPB, 0, s_side>>>(dst);
    scan_lookback_kernel<<<NBLK, SCAN_BS, 0, s_side>>>();
    csr_fill_kernel<<<(NE + TPB - 1) / TPB, TPB, 0, s_side>>>(src, dst);
    cudaEventRecord(s_join, s_side);

    cvt_x_kernel<<<(NN * 8 + TPB - 1) / TPB, TPB>>>(x);
    gemm_dual_kernel<64, true><<<gemm_blocks, 256>>>(Wl0, Wr0, b0);

    // ---- join: gather0 needs both CSR and bufAh/bufBh ----
    cudaStreamWaitEvent(0, s_join, 0);
    gather_kernel<64, true, true, true><<<gather_blocks64, 256>>>(nullptr);

    // ---- layer 1: 64 -> 64, ELU ----
    gemm_dual_kernel<64, true><<<gemm_blocks, 256>>>(Wl1, Wr1, b1);
    gather_kernel<64, true, true, true><<<gather_blocks64, 256>>>(nullptr);

    // ---- layer 2: 64 -> 32, no activation, straight to d_out ----
    gemm_dual_kernel<32, false><<<gemm_blocks, 256>>>(Wl2, Wr2, b2);
    gather_kernel<32, false, false, false><<<gather_blocks32, 256>>>(out);
}

// round 17
// speedup vs baseline: 1.0352x; 1.0061x over previous
#include <cuda_runtime.h>
#include <cuda_fp16.h>
#include <math.h>

#define NN 100000
#define NE 1600000
#define SCAN_BS 512
#define NBLK ((NN + SCAN_BS - 1) / SCAN_BS)   // 196

// -------- device scratch (allocation-free rule: __device__ globals) --------
// g_degi is a SELF-RESTORING invariant: statically zero at first call;
// scan_lookback re-zeroes each entry after consuming it, so every
// subsequent kernel_launch / graph replay starts from zeros again.
__device__ float  g_deginv[NN];
__device__ int    g_degi[NN];
__device__ int    g_rank[NE];                 // edge's rank within its dst row
__device__ int    g_rowptr[NN + 1];
__device__ unsigned long long g_scanstate[NBLK];  // lookback: (flag<<32)|value
__device__ int    g_col[NE];                  // CSR: src ids grouped by dst
__device__ __half g_bufAh[NN * 64];           // yl (fp16: gather reads this)
__device__ __half g_bufBh[NN * 64];           // yr (fp16, layers 0/1)
__device__ float  g_bufB[NN * 64];            // yr (fp32, final layer)
__device__ __half g_h16[NN * 64];             // activations, fp16 (GEMM A-feed)

// ---------------------------------------------------------------------------
// CSR build: deg_count(+rank, +scanstate reset) -> lookback scan(+degi reset)
//            -> fill (atomic-free).  3 kernels.
// ---------------------------------------------------------------------------
__global__ void deg_count_kernel(const int* __restrict__ dst) {
    int e = blockIdx.x * blockDim.x + threadIdx.x;
    if (e < NBLK) g_scanstate[e] = 0ULL;       // reset lookback state for scan
    if (e < NE) g_rank[e] = atomicAdd(&g_degi[dst[e]], 1);
}

// Single-pass decoupled-lookback exclusive scan of g_degi -> rowptr + deginv.
// Also re-zeroes g_degi (restores the invariant for the next replay).
__global__ void scan_lookback_kernel() {
    __shared__ int s[SCAN_BS];
    __shared__ int s_prefix;
    const int t = threadIdx.x;
    const int b = blockIdx.x;
    const int i = b * SCAN_BS + t;
    const int v = (i < NN) ? g_degi[i] : 0;
    s[t] = v;
    __syncthreads();
#pragma unroll
    for (int off = 1; off < SCAN_BS; off <<= 1) {
        int x = (t >= off) ? s[t - off] : 0;
        __syncthreads();
        s[t] += x;
        __syncthreads();
    }
    const int agg = s[SCAN_BS - 1];

    if (t == 0) {
        if (b == 0) {
            __threadfence();
            atomicExch(&g_scanstate[0], (2ULL << 32) | (unsigned)agg);
            s_prefix = 0;
        } else {
            __threadfence();
            atomicExch(&g_scanstate[b], (1ULL << 32) | (unsigned)agg);
            int running = 0;
            int p = b - 1;
            while (true) {
                unsigned long long st;
                do { st = atomicAdd(&g_scanstate[p], 0ULL); } while ((st >> 32) == 0ULL);
                running += (int)(st & 0xffffffffULL);
                if ((st >> 32) == 2ULL) break;
                p--;
            }
            __threadfence();
            atomicExch(&g_scanstate[b], (2ULL << 32) | (unsigned)(running + agg));
            s_prefix = running;
        }
    }
    __syncthreads();

    if (i < NN) {
        g_rowptr[i] = s_prefix + s[t] - v;         // exclusive prefix
        g_deginv[i] = 1.0f / fmaxf((float)v, 1.0f);
        g_degi[i] = 0;                             // restore invariant
    }
    if (i == 0) g_rowptr[NN] = NE;
}

// Atomic-free fill: position = rowptr[dst] + precomputed rank.
__global__ void csr_fill_kernel(const int* __restrict__ src,
                                const int* __restrict__ dst) {
    int e = blockIdx.x * blockDim.x + threadIdx.x;
    if (e >= NE) return;
    g_col[g_rowptr[dst[e]] + g_rank[e]] = src[e];
}

// ---------------------------------------------------------------------------
// fp16 pack helpers + f16 MMA
__device__ __forceinline__ unsigned pack_h2(float a, float b) {
    __half2 h = __floats2half2_rn(a, b);
    return *reinterpret_cast<unsigned*>(&h);
}
__device__ __forceinline__ unsigned pack_2h(__half a, __half b) {
    __half2 h = __halves2half2(a, b);
    return *reinterpret_cast<unsigned*>(&h);
}
__device__ __forceinline__ void mma_f16(float* d,
                                        unsigned a0, unsigned a1,
                                        unsigned a2, unsigned a3,
                                        unsigned b0, unsigned b1) {
    asm("mma.sync.aligned.m16n8k16.row.col.f32.f16.f16.f32 "
        "{%0,%1,%2,%3}, {%4,%5,%6,%7}, {%8,%9}, {%0,%1,%2,%3};"
        : "+f"(d[0]), "+f"(d[1]), "+f"(d[2]), "+f"(d[3])
        : "r"(a0), "r"(a1), "r"(a2), "r"(a3), "r"(b0), "r"(b1));
}

// ---------------------------------------------------------------------------
// Dual projection via fp16 tensor cores.
// FROM_X: layer 0 reads fp32 x with float2 vector loads, converting inline
//         (replaces the separate cvt_x kernel). Else A = g_h16.
// yl: 1 fp16 MMA.  yr: 2 fp16 MMAs (exact hi/lo fp16 split of Wr).
// YR16: store yr fp16 (layers 0/1); else fp32 (final layer).
template<int DOUT, bool FROM_X, bool YR16>
__global__ void __launch_bounds__(256)
gemm_dual_kernel(const float* __restrict__ x,
                 const float* __restrict__ Wl,
                 const float* __restrict__ Wr,
                 const float* __restrict__ bias) {
    constexpr int JT    = DOUT / 8;              // j-tiles (8 or 4)
    constexpr int FRAGS = 4 * JT;                // (kb, jt) fragments, kb of 16
    constexpr int FSZ   = FRAGS * 64;

    __shared__ unsigned sBl[FSZ];                // Wl fp16 pairs
    __shared__ unsigned sBrh[FSZ];               // Wr hi fp16 pairs
    __shared__ unsigned sBrl[FSZ];               // Wr lo fp16 pairs

    const int t    = threadIdx.x;
    const int wid  = t >> 5;
    const int lane = t & 31;
    const int gid  = lane >> 2;
    const int tig  = lane & 3;

    for (int idx = t; idx < FSZ; idx += 256) {
        const int frag = idx >> 6;
        const int li   = idx & 63;
        const int ln   = li >> 1;
        const int i    = li & 1;
        const int kb   = frag / JT;
        const int jt   = frag % JT;
        const int k    = kb * 16 + 2 * (ln & 3) + 8 * i;
        const int j    = jt * 8 + (ln >> 2);
        sBl[idx] = pack_h2(Wl[k * DOUT + j], Wl[(k + 1) * DOUT + j]);
        const float wr0 = Wr[k * DOUT + j];
        const float wr1 = Wr[(k + 1) * DOUT + j];
        const __half h0 = __float2half_rn(wr0);
        const __half h1 = __float2half_rn(wr1);
        sBrh[idx] = pack_2h(h0, h1);
        sBrl[idx] = pack_h2(wr0 - __half2float(h0), wr1 - __half2float(h1));
    }
    __syncthreads();

    const int node0 = blockIdx.x * 128 + wid * 16;
    const int r0 = node0 + gid;
    const bool ok0 = (r0 < NN);
    const bool ok1 = (r0 + 8 < NN);

    float dL[JT][4], dR[JT][4];
#pragma unroll
    for (int jt = 0; jt < JT; jt++) {
        float bc0 = bias[jt * 8 + 2 * tig];
        float bc1 = bias[jt * 8 + 2 * tig + 1];
        dL[jt][0] = dL[jt][1] = dL[jt][2] = dL[jt][3] = 0.f;
        dR[jt][0] = bc0; dR[jt][1] = bc1;
        dR[jt][2] = bc0; dR[jt][3] = bc1;
    }

#pragma unroll
    for (int kb = 0; kb < 4; kb++) {
        const int k0 = kb * 16;
        unsigned a0, a1, a2, a3;
        if (FROM_X) {
            float2 f;
            if (ok0) { f = *(const float2*)&x[(size_t)r0 * 64 + k0 + 2 * tig];
                       a0 = pack_h2(f.x, f.y); } else a0 = 0u;
            if (ok1) { f = *(const float2*)&x[(size_t)(r0 + 8) * 64 + k0 + 2 * tig];
                       a1 = pack_h2(f.x, f.y); } else a1 = 0u;
            if (ok0) { f = *(const float2*)&x[(size_t)r0 * 64 + k0 + 2 * tig + 8];
                       a2 = pack_h2(f.x, f.y); } else a2 = 0u;
            if (ok1) { f = *(const float2*)&x[(size_t)(r0 + 8) * 64 + k0 + 2 * tig + 8];
                       a3 = pack_h2(f.x, f.y); } else a3 = 0u;
        } else {
            a0 = ok0 ? *(const unsigned*)&g_h16[(size_t)r0 * 64 + k0 + 2 * tig] : 0u;
            a1 = ok1 ? *(const unsigned*)&g_h16[(size_t)(r0 + 8) * 64 + k0 + 2 * tig] : 0u;
            a2 = ok0 ? *(const unsigned*)&g_h16[(size_t)r0 * 64 + k0 + 2 * tig + 8] : 0u;
            a3 = ok1 ? *(const unsigned*)&g_h16[(size_t)(r0 + 8) * 64 + k0 + 2 * tig + 8] : 0u;
        }

#pragma unroll
        for (int jt = 0; jt < JT; jt++) {
            const int fbase = (kb * JT + jt) * 64 + lane * 2;
            const uint2 bl = *(const uint2*)&sBl[fbase];
            const uint2 bh = *(const uint2*)&sBrh[fbase];
            const uint2 bo = *(const uint2*)&sBrl[fbase];
            mma_f16(dL[jt], a0, a1, a2, a3, bl.x, bl.y);
            mma_f16(dR[jt], a0, a1, a2, a3, bh.x, bh.y);
            mma_f16(dR[jt], a0, a1, a2, a3, bo.x, bo.y);
        }
    }

    // epilogue: yl -> fp16; yr -> fp16 (YR16) or fp32
#pragma unroll
    for (int jt = 0; jt < JT; jt++) {
        const int j0 = jt * 8 + 2 * tig;
        if (ok0) {
            *(__half2*)&g_bufAh[(size_t)r0 * DOUT + j0] =
                __floats2half2_rn(dL[jt][0], dL[jt][1]);
            if (YR16)
                *(__half2*)&g_bufBh[(size_t)r0 * DOUT + j0] =
                    __floats2half2_rn(dR[jt][0], dR[jt][1]);
            else
                *(float2*)&g_bufB[(size_t)r0 * DOUT + j0] =
                    make_float2(dR[jt][0], dR[jt][1]);
        }
        if (ok1) {
            *(__half2*)&g_bufAh[(size_t)(r0 + 8) * DOUT + j0] =
                __floats2half2_rn(dL[jt][2], dL[jt][3]);
            if (YR16)
                *(__half2*)&g_bufBh[(size_t)(r0 + 8) * DOUT + j0] =
                    __floats2half2_rn(dR[jt][2], dR[jt][3]);
            else
                *(float2*)&g_bufB[(size_t)(r0 + 8) * DOUT + j0] =
                    make_float2(dR[jt][2], dR[jt][3]);
        }
    }
}

// ---------------------------------------------------------------------------
// Fused gather + epilogue: out[n] = [ELU]( mean_e yl_h16[col[e]] + yr[n] )
// Simple loop (round-13 form); yr read fp16 (YR16) or fp32.
template<int F, bool DO_ELU, bool TO_GH, bool YR16>
__global__ void __launch_bounds__(256)
gather_kernel(float* __restrict__ out_param) {
    constexpr int L = F / 8;               // lanes/node: 8 (F=64) or 4 (F=32)
    const int t    = threadIdx.x;
    const int grp  = t / L;
    const int lane = t % L;
    const int node = blockIdx.x * (256 / L) + grp;
    if (node >= NN) return;

    const int beg = g_rowptr[node];
    const int end = g_rowptr[node + 1];
    const __half* __restrict__ A = g_bufAh;

    float a[8] = {0.f, 0.f, 0.f, 0.f, 0.f, 0.f, 0.f, 0.f};
    for (int e = beg; e < end; e++) {
        const int s = g_col[e];
        const uint4 v = *(const uint4*)&A[(size_t)s * F + lane * 8];
        const __half2* hp = (const __half2*)&v;
        float2 f0 = __half22float2(hp[0]);
        float2 f1 = __half22float2(hp[1]);
        float2 f2 = __half22float2(hp[2]);
        float2 f3 = __half22float2(hp[3]);
        a[0] += f0.x; a[1] += f0.y;
        a[2] += f1.x; a[3] += f1.y;
        a[4] += f2.x; a[5] += f2.y;
        a[6] += f3.x; a[7] += f3.y;
    }

    const float di = g_deginv[node];
    float r[8];
    if (YR16) {
        const uint4 rv = *(const uint4*)&g_bufBh[(size_t)node * F + lane * 8];
        const __half2* rp = (const __half2*)&rv;
#pragma unroll
        for (int i = 0; i < 4; i++) {
            float2 f = __half22float2(rp[i]);
            r[2 * i] = f.x; r[2 * i + 1] = f.y;
        }
    } else {
        const float4 r0 = *(const float4*)&g_bufB[(size_t)node * F + lane * 8];
        const float4 r1 = *(const float4*)&g_bufB[(size_t)node * F + lane * 8 + 4];
        r[0] = r0.x; r[1] = r0.y; r[2] = r0.z; r[3] = r0.w;
        r[4] = r1.x; r[5] = r1.y; r[6] = r1.z; r[7] = r1.w;
    }

    float o[8];
#pragma unroll
    for (int i = 0; i < 8; i++) o[i] = fmaf(a[i], di, r[i]);
    if (DO_ELU) {
#pragma unroll
        for (int i = 0; i < 8; i++)
            o[i] = (o[i] > 0.f) ? o[i] : expm1f(o[i]);
    }
    if (TO_GH) {
        uint4 u;
        u.x = pack_h2(o[0], o[1]);
        u.y = pack_h2(o[2], o[3]);
        u.z = pack_h2(o[4], o[5]);
        u.w = pack_h2(o[6], o[7]);
        *(uint4*)&g_h16[(size_t)node * F + lane * 8] = u;
    } else {
        *(float4*)&out_param[(size_t)node * F + lane * 8] =
            make_float4(o[0], o[1], o[2], o[3]);
        *(float4*)&out_param[(size_t)node * F + lane * 8 + 4] =
            make_float4(o[4], o[5], o[6], o[7]);
    }
}

// ---------------------------------------------------------------------------
extern "C" void kernel_launch(void* const* d_in, const int* in_sizes, int n_in,
                              void* d_out, int out_size) {
    const float* x   = (const float*)d_in[0];
    const int*   ei  = (const int*)d_in[1];
    const float* Wl0 = (const float*)d_in[2];
    const float* Wr0 = (const float*)d_in[3];
    const float* b0  = (const float*)d_in[4];
    const float* Wl1 = (const float*)d_in[5];
    const float* Wr1 = (const float*)d_in[6];
    const float* b1  = (const float*)d_in[7];
    const float* Wl2 = (const float*)d_in[8];
    const float* Wr2 = (const float*)d_in[9];
    const float* b2  = (const float*)d_in[10];
    float* out = (float*)d_out;

    const int* src = ei;
    const int* dst = ei + NE;

    const int TPB = 256;
    const int gemm_blocks = (NN + 127) / 128;     // 782
    const int gather_blocks64 = (NN + 31) / 32;   // 32 nodes/block (L=8)
    const int gather_blocks32 = (NN + 63) / 64;   // 64 nodes/block (L=4)

    // One-time host-side setup (stream + events only).
    static cudaStream_t s_side = nullptr;
    static cudaEvent_t  s_fork = nullptr, s_join = nullptr;
    if (s_side == nullptr) {
        cudaStreamCreateWithFlags(&s_side, cudaStreamNonBlocking);
        cudaEventCreateWithFlags(&s_fork, cudaEventDisableTiming);
        cudaEventCreateWithFlags(&s_join, cudaEventDisableTiming);
    }

    // ---- fork: CSR build (3 kernels) on side stream, GEMM0 on main ----
    cudaEventRecord(s_fork, 0);
    cudaStreamWaitEvent(s_side, s_fork, 0);

    deg_count_kernel<<<(NE + TPB - 1) / TPB, TPB, 0, s_side>>>(dst);
    scan_lookback_kernel<<<NBLK, SCAN_BS, 0, s_side>>>();
    csr_fill_kernel<<<(NE + TPB - 1) / TPB, TPB, 0, s_side>>>(src, dst);
    cudaEventRecord(s_join, s_side);

    gemm_dual_kernel<64, true, true><<<gemm_blocks, 256>>>(x, Wl0, Wr0, b0);

    // ---- join: gather0 needs both CSR and bufAh/bufBh ----
    cudaStreamWaitEvent(0, s_join, 0);
    gather_kernel<64, true, true, true><<<gather_blocks64, 256>>>(nullptr);

    // ---- layer 1: 64 -> 64, ELU ----
    gemm_dual_kernel<64, false, true><<<gemm_blocks, 256>>>(nullptr, Wl1, Wr1, b1);
    gather_kernel<64, true, true, true><<<gather_blocks64, 256>>>(nullptr);

    // ---- layer 2: 64 -> 32, no activation, straight to d_out ----
    gemm_dual_kernel<32, false, false><<<gemm_blocks, 256>>>(nullptr, Wl2, Wr2, b2);
    gather_kernel<32, false, false, false><<<gather_blocks32, 256>>>(out);
}